// round 15
// baseline (speedup 1.0000x reference)
#include <cuda_runtime.h>
#include <cuda_bf16.h>
#include <cstdint>

#define BB 4
#define TT 4096
#define DM 1024
#define DH 64

// scratch (allocation-free rule: __device__ globals)
__device__ float g_L[BB * TT];
__device__ __nv_bfloat16 g_wh[3 * DH * DM];
__device__ __nv_bfloat16 g_wl[3 * DH * DM];
__device__ __nv_bfloat16 g_qh[BB * TT * DH];
__device__ __nv_bfloat16 g_ql[BB * TT * DH];
__device__ __nv_bfloat16 g_kh[BB * TT * DH];
__device__ __nv_bfloat16 g_kl[BB * TT * DH];
__device__ __nv_bfloat16 g_vh[BB * TT * DH];
__device__ __nv_bfloat16 g_vl[BB * TT * DH];

// ===========================================================================
// base-ISA helpers
// ===========================================================================
__device__ __forceinline__ uint32_t smem_u32(const void* p) {
    uint32_t a;
    asm("{ .reg .u64 t; cvta.to.shared.u64 t, %1; cvt.u32.u64 %0, t; }"
        : "=r"(a) : "l"(p));
    return a;
}
__device__ __forceinline__ void cp16(uint32_t dst, const void* src) {
    asm volatile("cp.async.cg.shared.global [%0], [%1], 16;"
                 :: "r"(dst), "l"(src) : "memory");
}
#define CP_COMMIT() asm volatile("cp.async.commit_group;" ::: "memory")
#define CP_WAIT0()  asm volatile("cp.async.wait_group 0;" ::: "memory")

#define LDMX4(r, addr)                                                       \
    asm volatile("ldmatrix.sync.aligned.m8n8.x4.shared.b16 {%0,%1,%2,%3}, [%4];" \
        : "=r"((r)[0]), "=r"((r)[1]), "=r"((r)[2]), "=r"((r)[3]) : "r"(addr))
#define LDMX4T(r, addr)                                                      \
    asm volatile("ldmatrix.sync.aligned.m8n8.x4.trans.shared.b16 {%0,%1,%2,%3}, [%4];" \
        : "=r"((r)[0]), "=r"((r)[1]), "=r"((r)[2]), "=r"((r)[3]) : "r"(addr))

__device__ __forceinline__ void mma16816(float* d, const uint32_t* a,
                                         uint32_t b0, uint32_t b1) {
    asm volatile(
        "mma.sync.aligned.m16n8k16.row.col.f32.bf16.bf16.f32 "
        "{%0,%1,%2,%3}, {%4,%5,%6,%7}, {%8,%9}, {%0,%1,%2,%3};"
        : "+f"(d[0]), "+f"(d[1]), "+f"(d[2]), "+f"(d[3])
        : "r"(a[0]), "r"(a[1]), "r"(a[2]), "r"(a[3]), "r"(b0), "r"(b1));
}

// fast exp2 (MUFU.EX2)
__device__ __forceinline__ float ex2f(float x) {
    float r;
    asm("ex2.approx.ftz.f32 %0, %1;" : "=f"(r) : "f"(x));
    return r;
}

// fast bf16 hi/lo split of a float pair (hi reconstruction via bit ops)
__device__ __forceinline__ void split_pack_fast(float f0, float f1,
                                                uint32_t& h, uint32_t& l) {
    asm("cvt.rn.bf16x2.f32 %0, %2, %1;" : "=r"(h) : "f"(f0), "f"(f1));
    const float h0f = __uint_as_float(h << 16);
    const float h1f = __uint_as_float(h & 0xffff0000u);
    const float r0 = f0 - h0f, r1 = f1 - h1f;
    asm("cvt.rn.bf16x2.f32 %0, %2, %1;" : "=r"(l) : "f"(r0), "f"(r1));
}

#define LOG2E 1.44269504f

// ===========================================================================
// zero out + g_L (d_out is poisoned by harness; atomics need zeros)
// 8 floats per thread. out: 1048576 floats -> 131072 slots; g_L: 16384 -> 2048.
// ===========================================================================
__global__ void __launch_bounds__(256) zero_kernel(float* __restrict__ out)
{
    const int i = blockIdx.x * 256 + threadIdx.x;
    const float4 z = make_float4(0.f, 0.f, 0.f, 0.f);
    if (i < 131072) {
        *(float4*)(out + (size_t)i * 8) = z;
        *(float4*)(out + (size_t)i * 8 + 4) = z;
    } else {
        const int j = i - 131072;   // 0..2047
        *(float4*)(g_L + (size_t)j * 8) = z;
        *(float4*)(g_L + (size_t)j * 8 + 4) = z;
    }
}

// ===========================================================================
// convert W: fp32 -> (hi, lo) bf16
// ===========================================================================
__global__ void __launch_bounds__(256) convert_w_kernel(
    const float* __restrict__ Wq, const float* __restrict__ Wk,
    const float* __restrict__ Wv)
{
    const float* W = (blockIdx.y == 0) ? Wq : (blockIdx.y == 1) ? Wk : Wv;
    const size_t base = (size_t)blockIdx.y * DH * DM;
    const int i4 = blockIdx.x * 256 + threadIdx.x;
    float4 f = *(const float4*)(W + (size_t)i4 * 4);
    uint32_t h01, l01, h23, l23;
    split_pack_fast(f.x, f.y, h01, l01);
    split_pack_fast(f.z, f.w, h23, l23);
    *(uint2*)(g_wh + base + (size_t)i4 * 4) = make_uint2(h01, h23);
    *(uint2*)(g_wl + base + (size_t)i4 * 4) = make_uint2(l01, l23);
}

// ===========================================================================
// HMMA projection with fused x-conversion (M=128, Kc=64).
// ===========================================================================
#define PSTR 72
#define A_ELE (128 * PSTR)
#define B_ELE (64 * PSTR)
#define BUF_ELE (2 * A_ELE + 6 * B_ELE)
#define PJ_SMEM (2 * BUF_ELE * 2)

__device__ __forceinline__ void pj_load_B(uint32_t sbase, int k0, int buf)
{
    const int tid = threadIdx.x;
    const uint32_t bofs = sbase + buf * BUF_ELE * 2;
    #pragma unroll
    for (int i = 0; i < 12; i++) {
        const int idx = tid + 256 * i;
        const int t = idx >> 9;
        const int rem = idx & 511;
        const int r = rem >> 3, g = rem & 7;
        const int o = t >> 1;
        const __nv_bfloat16* src = ((t & 1) ? g_wl : g_wh)
            + (size_t)o * DH * DM + (size_t)r * DM + k0 + g * 8;
        cp16(bofs + (2 * A_ELE + t * B_ELE + r * PSTR + g * 8) * 2, src);
    }
}
__device__ __forceinline__ void pj_load_A_regs(const float* __restrict__ x,
                                               int m0, int k0, float4* ra)
{
    const int tid = threadIdx.x;
    #pragma unroll
    for (int i = 0; i < 8; i++) {
        const int idx = tid + 256 * i;
        const int r = idx >> 4, g = idx & 15;
        ra[i] = *(const float4*)(x + (size_t)(m0 + r) * DM + k0 + g * 4);
    }
}
__device__ __forceinline__ void pj_store_A(char* smembytes, const float4* ra, int buf)
{
    const int tid = threadIdx.x;
    const uint32_t bofs = buf * BUF_ELE * 2;
    #pragma unroll
    for (int i = 0; i < 8; i++) {
        const int idx = tid + 256 * i;
        const int r = idx >> 4, g = idx & 15;
        uint32_t h01, l01, h23, l23;
        split_pack_fast(ra[i].x, ra[i].y, h01, l01);
        split_pack_fast(ra[i].z, ra[i].w, h23, l23);
        const uint32_t so = (r * PSTR + g * 4) * 2;
        *(uint2*)(smembytes + bofs + so) = make_uint2(h01, h23);
        *(uint2*)(smembytes + bofs + A_ELE * 2 + so) = make_uint2(l01, l23);
    }
}

__global__ void __launch_bounds__(256) proj_mma_kernel(const float* __restrict__ x)
{
    extern __shared__ char smemb[];
    const uint32_t sbase = smem_u32(smemb);
    const int tid = threadIdx.x;
    const int wid = tid >> 5, lane = tid & 31;
    const int warp_m = wid >> 1, warp_n = wid & 1;
    const int m0 = blockIdx.x * 128;

    float acc[3][2][4][4];
    #pragma unroll
    for (int o = 0; o < 3; o++)
        #pragma unroll
        for (int mt = 0; mt < 2; mt++)
            #pragma unroll
            for (int nt = 0; nt < 4; nt++)
                #pragma unroll
                for (int e = 0; e < 4; e++) acc[o][mt][nt][e] = 0.f;

    float4 ra[8];
    pj_load_A_regs(x, m0, 0, ra);
    pj_load_B(sbase, 0, 0);
    CP_COMMIT();
    pj_store_A(smemb, ra, 0);
    CP_WAIT0();
    __syncthreads();

    const int arow = lane & 15, ahalf = lane >> 4;
    const int bq = lane >> 3, bw = lane & 7;
    const int brow = (bq >> 1) * 8 + bw;
    const int bk = (bq & 1) * 8;

    for (int c = 0; c < 16; c++) {
        const int buf = c & 1;
        if (c < 15) {
            pj_load_A_regs(x, m0, (c + 1) * 64, ra);
            pj_load_B(sbase, (c + 1) * 64, buf ^ 1);
            CP_COMMIT();
        }
        const uint32_t abase = sbase + buf * BUF_ELE * 2;
        #pragma unroll
        for (int ks = 0; ks < 4; ks++) {
            const int kc = ks * 16;
            uint32_t ah[2][4], al[2][4];
            #pragma unroll
            for (int mt = 0; mt < 2; mt++) {
                const uint32_t addr = abase
                    + ((warp_m * 32 + mt * 16 + arow) * PSTR + kc + ahalf * 8) * 2;
                LDMX4(ah[mt], addr);
                LDMX4(al[mt], addr + A_ELE * 2);
            }
            #pragma unroll
            for (int o = 0; o < 3; o++) {
                const uint32_t btile = abase + (2 * A_ELE + (o * 2) * B_ELE) * 2;
                uint32_t bh[2][4], bl[2][4];
                #pragma unroll
                for (int np = 0; np < 2; np++) {
                    const uint32_t addr = btile
                        + ((warp_n * 32 + np * 16 + brow) * PSTR + kc + bk) * 2;
                    LDMX4(bh[np], addr);
                    LDMX4(bl[np], addr + B_ELE * 2);
                }
                #pragma unroll
                for (int mt = 0; mt < 2; mt++)
                    #pragma unroll
                    for (int np = 0; np < 2; np++) {
                        mma16816(acc[o][mt][2 * np],     ah[mt], bh[np][0], bh[np][1]);
                        mma16816(acc[o][mt][2 * np + 1], ah[mt], bh[np][2], bh[np][3]);
                        mma16816(acc[o][mt][2 * np],     ah[mt], bl[np][0], bl[np][1]);
                        mma16816(acc[o][mt][2 * np + 1], ah[mt], bl[np][2], bl[np][3]);
                        mma16816(acc[o][mt][2 * np],     al[mt], bh[np][0], bh[np][1]);
                        mma16816(acc[o][mt][2 * np + 1], al[mt], bh[np][2], bh[np][3]);
                    }
            }
        }
        if (c < 15) {
            pj_store_A(smemb, ra, buf ^ 1);
            CP_WAIT0();
        }
        __syncthreads();
    }

    const int frow = lane >> 2, fcol = (lane & 3) * 2;
    #pragma unroll
    for (int o = 0; o < 3; o++) {
        __nv_bfloat16* oh = (o == 0) ? g_qh : (o == 1) ? g_kh : g_vh;
        __nv_bfloat16* ol = (o == 0) ? g_ql : (o == 1) ? g_kl : g_vl;
        #pragma unroll
        for (int mt = 0; mt < 2; mt++)
            #pragma unroll
            for (int nt = 0; nt < 4; nt++) {
                const int row = m0 + warp_m * 32 + mt * 16 + frow;
                const int col = warp_n * 32 + nt * 8 + fcol;
                uint32_t h01, l01, h23, l23;
                split_pack_fast(acc[o][mt][nt][0], acc[o][mt][nt][1], h01, l01);
                split_pack_fast(acc[o][mt][nt][2], acc[o][mt][nt][3], h23, l23);
                *(uint32_t*)(oh + (size_t)row * DH + col) = h01;
                *(uint32_t*)(ol + (size_t)row * DH + col) = l01;
                *(uint32_t*)(oh + (size_t)(row + 8) * DH + col) = h23;
                *(uint32_t*)(ol + (size_t)(row + 8) * DH + col) = l23;
            }
    }
}

// ===========================================================================
// HMMA split-KV flash attention. Br=128, Bc=64, 256 thr.
// Epilogue: atomicAdd unnormalized O into d_out, row sums into g_L.
// ===========================================================================
#define AST 72
#define AT_QH 0
#define AT_QL 9216
#define AT_TB 18432
#define AT_TBSZ 18432
#define AT_SMEM ((AT_TB + 2 * AT_TBSZ) * 2)   // 110592 bytes

__device__ __forceinline__ void at_load(uint32_t sbase, int b, int j0, int buf)
{
    const int tid = threadIdx.x;
    const uint32_t bb = sbase + (AT_TB + buf * AT_TBSZ) * 2;
    #pragma unroll
    for (int i = 0; i < 2; i++) {
        const int idx = tid + 256 * i;
        const int r = idx >> 3, g = idx & 7;
        const size_t go = (size_t)(b * TT + j0 + r) * DH + g * 8;
        const uint32_t so = (r * AST + g * 8) * 2;
        cp16(bb + so,         g_kh + go);
        cp16(bb + 9216 + so,  g_kl + go);
        cp16(bb + 18432 + so, g_vh + go);
        cp16(bb + 27648 + so, g_vl + go);
    }
}

__global__ void __launch_bounds__(256) attn_mma_kernel(
    const float* __restrict__ rel_emb, float* __restrict__ out)
{
    const int rt    = 31 - blockIdx.x;   // big rt first
    const int chunk = blockIdx.y;
    const int b     = blockIdx.z;
    const int ct0   = chunk * 8;
    const int ctmax = 2 * rt + 1;
    if (ct0 > ctmax) return;
    const int ct1 = min(ctmax, ct0 + 7);

    extern __shared__ char smemb[];
    const uint32_t sbase = smem_u32(smemb);
    __shared__ float sRel[17];

    const int tid = threadIdx.x;
    const int w = tid >> 5, lane = tid & 31;
    const int i0 = rt * 128;

    if (tid < 17) sRel[tid] = rel_emb[tid] * LOG2E;
    const float SCL = 0.125f * LOG2E;

    #pragma unroll
    for (int it = 0; it < 4; it++) {
        const int idx = tid + 256 * it;
        const int r = idx >> 3, g = idx & 7;
        const size_t go = (size_t)(b * TT + i0 + r) * DH + g * 8;
        const uint32_t so = (r * AST + g * 8) * 2;
        cp16(sbase + AT_QH * 2 + so, g_qh + go);
        cp16(sbase + AT_QL * 2 + so, g_ql + go);
    }
    at_load(sbase, b, ct0 * 64, 0);
    CP_COMMIT();

    const int arow = lane & 15, ahalf = lane >> 4;
    const int bq = lane >> 3, bw = lane & 7;
    const int brow = (bq >> 1) * 8 + bw;
    const int bk = (bq & 1) * 8;
    const int frow = lane >> 2, fcol = (lane & 3) * 2;
    const int vrow = (bq & 1) * 8 + bw;
    const int vcol = (bq >> 1) * 8;

    float oacc[8][4];
    #pragma unroll
    for (int nt = 0; nt < 8; nt++)
        #pragma unroll
        for (int e = 0; e < 4; e++) oacc[nt][e] = 0.f;
    float l0 = 0.f, l1 = 0.f;

    for (int ct = ct0; ct <= ct1; ct++) {
        const int buf = (ct - ct0) & 1;
        CP_WAIT0();
        __syncthreads();
        if (ct < ct1) {
            at_load(sbase, b, (ct + 1) * 64, buf ^ 1);
            CP_COMMIT();
        }

        const uint32_t tb = sbase + (AT_TB + buf * AT_TBSZ) * 2;
        const int j0 = ct * 64;

        // ---- S = Q K^T ----
        float sacc[8][4];
        #pragma unroll
        for (int nt = 0; nt < 8; nt++)
            #pragma unroll
            for (int e = 0; e < 4; e++) sacc[nt][e] = 0.f;
        #pragma unroll
        for (int ks = 0; ks < 4; ks++) {
            const int kc = ks * 16;
            uint32_t ah[4], al[4];
            const uint32_t aaddr = sbase
                + ((w * 16 + arow) * AST + kc + ahalf * 8) * 2;
            LDMX4(ah, aaddr + AT_QH * 2);
            LDMX4(al, aaddr + AT_QL * 2);
            #pragma unroll
            for (int nt16 = 0; nt16 < 4; nt16++) {
                uint32_t bh[4], bl[4];
                const uint32_t baddr = tb + ((nt16 * 16 + brow) * AST + kc + bk) * 2;
                LDMX4(bh, baddr);
                LDMX4(bl, baddr + 9216);
                mma16816(sacc[2 * nt16],     ah, bh[0], bh[1]);
                mma16816(sacc[2 * nt16 + 1], ah, bh[2], bh[3]);
                mma16816(sacc[2 * nt16],     ah, bl[0], bl[1]);
                mma16816(sacc[2 * nt16 + 1], ah, bl[2], bl[3]);
                mma16816(sacc[2 * nt16],     al, bh[0], bh[1]);
                mma16816(sacc[2 * nt16 + 1], al, bh[2], bh[3]);
            }
        }

        // ---- bias + exp2 (+ mask), accumulate l ----
        float e[8][4];
        const float b0v = sRel[0];
        if (ct <= 2 * rt - 2) {
            #pragma unroll
            for (int nt = 0; nt < 8; nt++)
                #pragma unroll
                for (int u = 0; u < 4; u++)
                    e[nt][u] = ex2f(fmaf(sacc[nt][u], SCL, b0v));
        } else {
            const int ia = i0 + w * 16 + frow;
            #pragma unroll
            for (int nt = 0; nt < 8; nt++) {
                const int jb2 = j0 + nt * 8 + fcol;
                #pragma unroll
                for (int u = 0; u < 4; u++) {
                    const int j = jb2 + (u & 1);
                    const int i = ia + (u >> 1) * 8;
                    const int d = j - i;
                    e[nt][u] = (d <= 0)
                        ? ex2f(fmaf(sacc[nt][u], SCL, sRel[(d < -8 ? -8 : d) + 8]))
                        : 0.f;
                }
            }
        }
        #pragma unroll
        for (int nt = 0; nt < 8; nt++) {
            l0 += e[nt][0] + e[nt][1];
            l1 += e[nt][2] + e[nt][3];
        }

        // ---- P fragments (accumulator layout == A-operand layout) ----
        uint32_t pah[4][4], pal[4][4];
        #pragma unroll
        for (int t = 0; t < 4; t++) {
            split_pack_fast(e[2 * t][0],     e[2 * t][1],     pah[t][0], pal[t][0]);
            split_pack_fast(e[2 * t][2],     e[2 * t][3],     pah[t][1], pal[t][1]);
            split_pack_fast(e[2 * t + 1][0], e[2 * t + 1][1], pah[t][2], pal[t][2]);
            split_pack_fast(e[2 * t + 1][2], e[2 * t + 1][3], pah[t][3], pal[t][3]);
        }

        // ---- O += P V (V natural layout, trans ldmatrix) ----
        #pragma unroll
        for (int js = 0; js < 4; js++) {
            const int jc = js * 16;
            #pragma unroll
            for (int h16 = 0; h16 < 4; h16++) {
                uint32_t vh4[4], vl4[4];
                const uint32_t vaddr = tb
                    + ((jc + vrow) * AST + h16 * 16 + vcol) * 2;
                LDMX4T(vh4, vaddr + 18432);
                LDMX4T(vl4, vaddr + 27648);
                mma16816(oacc[2 * h16],     pah[js], vh4[0], vh4[1]);
                mma16816(oacc[2 * h16 + 1], pah[js], vh4[2], vh4[3]);
                mma16816(oacc[2 * h16],     pah[js], vl4[0], vl4[1]);
                mma16816(oacc[2 * h16 + 1], pah[js], vl4[2], vl4[3]);
                mma16816(oacc[2 * h16],     pal[js], vh4[0], vh4[1]);
                mma16816(oacc[2 * h16 + 1], pal[js], vh4[2], vh4[3]);
            }
        }
    }

    // reduce l within quads (lanes sharing rows)
    l0 += __shfl_xor_sync(0xffffffffu, l0, 1);
    l0 += __shfl_xor_sync(0xffffffffu, l0, 2);
    l1 += __shfl_xor_sync(0xffffffffu, l1, 1);
    l1 += __shfl_xor_sync(0xffffffffu, l1, 2);

    // epilogue: atomic accumulate into out (L2-resident) + g_L
    const int row = w * 16 + frow;
    float* op0 = out + (size_t)(b * TT + i0 + row) * DH;
    float* op1 = op0 + (size_t)8 * DH;
    #pragma unroll
    for (int nt = 0; nt < 8; nt++) {
        const int col = nt * 8 + fcol;
        atomicAdd(op0 + col,     oacc[nt][0]);
        atomicAdd(op0 + col + 1, oacc[nt][1]);
        atomicAdd(op1 + col,     oacc[nt][2]);
        atomicAdd(op1 + col + 1, oacc[nt][3]);
    }
    if ((lane & 3) == 0) {
        atomicAdd(g_L + b * TT + i0 + row,     l0);
        atomicAdd(g_L + b * TT + i0 + row + 8, l1);
    }
}

// ---------------------------------------------------------------------------
// Normalize: out[row, :] /= L[row].  512 blocks x 256 thr x 8 floats.
// ---------------------------------------------------------------------------
__global__ void __launch_bounds__(256) normalize_kernel(float* __restrict__ out)
{
    const int i = blockIdx.x * 256 + threadIdx.x;     // 0..131071
    const int row = i >> 3;                           // global row 0..16383
    const float inv = 1.0f / g_L[row];
    float* p = out + (size_t)i * 8;
    float4 v0 = *(float4*)(p);
    float4 v1 = *(float4*)(p + 4);
    *(float4*)(p)     = make_float4(v0.x * inv, v0.y * inv, v0.z * inv, v0.w * inv);
    *(float4*)(p + 4) = make_float4(v1.x * inv, v1.y * inv, v1.z * inv, v1.w * inv);
}

extern "C" void kernel_launch(void* const* d_in, const int* in_sizes, int n_in,
                              void* d_out, int out_size)
{
    const float* x   = (const float*)d_in[0];
    const float* Wq  = (const float*)d_in[1];
    const float* Wk  = (const float*)d_in[2];
    const float* Wv  = (const float*)d_in[3];
    const float* rel = (const float*)d_in[4];
    float* out = (float*)d_out;

    zero_kernel<<<520, 256>>>(out);

    dim3 wgrid(64, 3);
    convert_w_kernel<<<wgrid, 256>>>(Wq, Wk, Wv);

    cudaFuncSetAttribute(proj_mma_kernel,
                         cudaFuncAttributeMaxDynamicSharedMemorySize, PJ_SMEM);
    proj_mma_kernel<<<128, 256, PJ_SMEM>>>(x);

    cudaFuncSetAttribute(attn_mma_kernel,
                         cudaFuncAttributeMaxDynamicSharedMemorySize, AT_SMEM);
    dim3 agrid(32, 8, BB);
    attn_mma_kernel<<<agrid, 256, AT_SMEM>>>(rel, out);

    normalize_kernel<<<512, 256>>>(out);
}

// round 16
// speedup vs baseline: 1.0331x; 1.0331x over previous
#include <cuda_runtime.h>
#include <cuda_bf16.h>
#include <cstdint>

#define BB 4
#define TT 4096
#define DM 1024
#define DH 64

// scratch (allocation-free rule: __device__ globals)
__device__ float g_po[BB * 32 * 8 * 128 * 64];
__device__ float g_pl[BB * 32 * 8 * 128];
__device__ __nv_bfloat16 g_wh[3 * DH * DM];
__device__ __nv_bfloat16 g_wl[3 * DH * DM];
__device__ __nv_bfloat16 g_qh[BB * TT * DH];
__device__ __nv_bfloat16 g_ql[BB * TT * DH];
__device__ __nv_bfloat16 g_kh[BB * TT * DH];
__device__ __nv_bfloat16 g_kl[BB * TT * DH];
__device__ __nv_bfloat16 g_vh[BB * TT * DH];
__device__ __nv_bfloat16 g_vl[BB * TT * DH];

// ===========================================================================
// base-ISA helpers
// ===========================================================================
__device__ __forceinline__ uint32_t smem_u32(const void* p) {
    uint32_t a;
    asm("{ .reg .u64 t; cvta.to.shared.u64 t, %1; cvt.u32.u64 %0, t; }"
        : "=r"(a) : "l"(p));
    return a;
}
__device__ __forceinline__ void cp16(uint32_t dst, const void* src) {
    asm volatile("cp.async.cg.shared.global [%0], [%1], 16;"
                 :: "r"(dst), "l"(src) : "memory");
}
#define CP_COMMIT() asm volatile("cp.async.commit_group;" ::: "memory")
#define CP_WAIT0()  asm volatile("cp.async.wait_group 0;" ::: "memory")

#define LDMX4(r, addr)                                                       \
    asm volatile("ldmatrix.sync.aligned.m8n8.x4.shared.b16 {%0,%1,%2,%3}, [%4];" \
        : "=r"((r)[0]), "=r"((r)[1]), "=r"((r)[2]), "=r"((r)[3]) : "r"(addr))
#define LDMX4T(r, addr)                                                      \
    asm volatile("ldmatrix.sync.aligned.m8n8.x4.trans.shared.b16 {%0,%1,%2,%3}, [%4];" \
        : "=r"((r)[0]), "=r"((r)[1]), "=r"((r)[2]), "=r"((r)[3]) : "r"(addr))

__device__ __forceinline__ void mma16816(float* d, const uint32_t* a,
                                         uint32_t b0, uint32_t b1) {
    asm volatile(
        "mma.sync.aligned.m16n8k16.row.col.f32.bf16.bf16.f32 "
        "{%0,%1,%2,%3}, {%4,%5,%6,%7}, {%8,%9}, {%0,%1,%2,%3};"
        : "+f"(d[0]), "+f"(d[1]), "+f"(d[2]), "+f"(d[3])
        : "r"(a[0]), "r"(a[1]), "r"(a[2]), "r"(a[3]), "r"(b0), "r"(b1));
}

// fast exp2 (MUFU.EX2)
__device__ __forceinline__ float ex2f(float x) {
    float r;
    asm("ex2.approx.ftz.f32 %0, %1;" : "=f"(r) : "f"(x));
    return r;
}

// fast bf16 hi/lo split of a float pair (hi reconstruction via bit ops)
__device__ __forceinline__ void split_pack_fast(float f0, float f1,
                                                uint32_t& h, uint32_t& l) {
    asm("cvt.rn.bf16x2.f32 %0, %2, %1;" : "=r"(h) : "f"(f0), "f"(f1));
    const float h0f = __uint_as_float(h << 16);
    const float h1f = __uint_as_float(h & 0xffff0000u);
    const float r0 = f0 - h0f, r1 = f1 - h1f;
    asm("cvt.rn.bf16x2.f32 %0, %2, %1;" : "=r"(l) : "f"(r0), "f"(r1));
}

#define LOG2E 1.44269504f

// ===========================================================================
// convert W: fp32 -> (hi, lo) bf16
// ===========================================================================
__global__ void __launch_bounds__(256) convert_w_kernel(
    const float* __restrict__ Wq, const float* __restrict__ Wk,
    const float* __restrict__ Wv)
{
    const float* W = (blockIdx.y == 0) ? Wq : (blockIdx.y == 1) ? Wk : Wv;
    const size_t base = (size_t)blockIdx.y * DH * DM;
    const int i4 = blockIdx.x * 256 + threadIdx.x;
    float4 f = *(const float4*)(W + (size_t)i4 * 4);
    uint32_t h01, l01, h23, l23;
    split_pack_fast(f.x, f.y, h01, l01);
    split_pack_fast(f.z, f.w, h23, l23);
    *(uint2*)(g_wh + base + (size_t)i4 * 4) = make_uint2(h01, h23);
    *(uint2*)(g_wl + base + (size_t)i4 * 4) = make_uint2(l01, l23);
}

// ===========================================================================
// HMMA projection with fused x-conversion (M=128, Kc=64).
// ===========================================================================
#define PSTR 72
#define A_ELE (128 * PSTR)
#define B_ELE (64 * PSTR)
#define BUF_ELE (2 * A_ELE + 6 * B_ELE)
#define PJ_SMEM (2 * BUF_ELE * 2)

__device__ __forceinline__ void pj_load_B(uint32_t sbase, int k0, int buf)
{
    const int tid = threadIdx.x;
    const uint32_t bofs = sbase + buf * BUF_ELE * 2;
    #pragma unroll
    for (int i = 0; i < 12; i++) {
        const int idx = tid + 256 * i;
        const int t = idx >> 9;
        const int rem = idx & 511;
        const int r = rem >> 3, g = rem & 7;
        const int o = t >> 1;
        const __nv_bfloat16* src = ((t & 1) ? g_wl : g_wh)
            + (size_t)o * DH * DM + (size_t)r * DM + k0 + g * 8;
        cp16(bofs + (2 * A_ELE + t * B_ELE + r * PSTR + g * 8) * 2, src);
    }
}
__device__ __forceinline__ void pj_load_A_regs(const float* __restrict__ x,
                                               int m0, int k0, float4* ra)
{
    const int tid = threadIdx.x;
    #pragma unroll
    for (int i = 0; i < 8; i++) {
        const int idx = tid + 256 * i;
        const int r = idx >> 4, g = idx & 15;
        ra[i] = *(const float4*)(x + (size_t)(m0 + r) * DM + k0 + g * 4);
    }
}
__device__ __forceinline__ void pj_store_A(char* smembytes, const float4* ra, int buf)
{
    const int tid = threadIdx.x;
    const uint32_t bofs = buf * BUF_ELE * 2;
    #pragma unroll
    for (int i = 0; i < 8; i++) {
        const int idx = tid + 256 * i;
        const int r = idx >> 4, g = idx & 15;
        uint32_t h01, l01, h23, l23;
        split_pack_fast(ra[i].x, ra[i].y, h01, l01);
        split_pack_fast(ra[i].z, ra[i].w, h23, l23);
        const uint32_t so = (r * PSTR + g * 4) * 2;
        *(uint2*)(smembytes + bofs + so) = make_uint2(h01, h23);
        *(uint2*)(smembytes + bofs + A_ELE * 2 + so) = make_uint2(l01, l23);
    }
}

__global__ void __launch_bounds__(256) proj_mma_kernel(const float* __restrict__ x)
{
    extern __shared__ char smemb[];
    const uint32_t sbase = smem_u32(smemb);
    const int tid = threadIdx.x;
    const int wid = tid >> 5, lane = tid & 31;
    const int warp_m = wid >> 1, warp_n = wid & 1;
    const int m0 = blockIdx.x * 128;

    float acc[3][2][4][4];
    #pragma unroll
    for (int o = 0; o < 3; o++)
        #pragma unroll
        for (int mt = 0; mt < 2; mt++)
            #pragma unroll
            for (int nt = 0; nt < 4; nt++)
                #pragma unroll
                for (int e = 0; e < 4; e++) acc[o][mt][nt][e] = 0.f;

    float4 ra[8];
    pj_load_A_regs(x, m0, 0, ra);
    pj_load_B(sbase, 0, 0);
    CP_COMMIT();
    pj_store_A(smemb, ra, 0);
    CP_WAIT0();
    __syncthreads();

    const int arow = lane & 15, ahalf = lane >> 4;
    const int bq = lane >> 3, bw = lane & 7;
    const int brow = (bq >> 1) * 8 + bw;
    const int bk = (bq & 1) * 8;

    for (int c = 0; c < 16; c++) {
        const int buf = c & 1;
        if (c < 15) {
            pj_load_A_regs(x, m0, (c + 1) * 64, ra);
            pj_load_B(sbase, (c + 1) * 64, buf ^ 1);
            CP_COMMIT();
        }
        const uint32_t abase = sbase + buf * BUF_ELE * 2;
        #pragma unroll
        for (int ks = 0; ks < 4; ks++) {
            const int kc = ks * 16;
            uint32_t ah[2][4], al[2][4];
            #pragma unroll
            for (int mt = 0; mt < 2; mt++) {
                const uint32_t addr = abase
                    + ((warp_m * 32 + mt * 16 + arow) * PSTR + kc + ahalf * 8) * 2;
                LDMX4(ah[mt], addr);
                LDMX4(al[mt], addr + A_ELE * 2);
            }
            #pragma unroll
            for (int o = 0; o < 3; o++) {
                const uint32_t btile = abase + (2 * A_ELE + (o * 2) * B_ELE) * 2;
                uint32_t bh[2][4], bl[2][4];
                #pragma unroll
                for (int np = 0; np < 2; np++) {
                    const uint32_t addr = btile
                        + ((warp_n * 32 + np * 16 + brow) * PSTR + kc + bk) * 2;
                    LDMX4(bh[np], addr);
                    LDMX4(bl[np], addr + B_ELE * 2);
                }
                #pragma unroll
                for (int mt = 0; mt < 2; mt++)
                    #pragma unroll
                    for (int np = 0; np < 2; np++) {
                        mma16816(acc[o][mt][2 * np],     ah[mt], bh[np][0], bh[np][1]);
                        mma16816(acc[o][mt][2 * np + 1], ah[mt], bh[np][2], bh[np][3]);
                        mma16816(acc[o][mt][2 * np],     ah[mt], bl[np][0], bl[np][1]);
                        mma16816(acc[o][mt][2 * np + 1], ah[mt], bl[np][2], bl[np][3]);
                        mma16816(acc[o][mt][2 * np],     al[mt], bh[np][0], bh[np][1]);
                        mma16816(acc[o][mt][2 * np + 1], al[mt], bh[np][2], bh[np][3]);
                    }
            }
        }
        if (c < 15) {
            pj_store_A(smemb, ra, buf ^ 1);
            CP_WAIT0();
        }
        __syncthreads();
    }

    const int frow = lane >> 2, fcol = (lane & 3) * 2;
    #pragma unroll
    for (int o = 0; o < 3; o++) {
        __nv_bfloat16* oh = (o == 0) ? g_qh : (o == 1) ? g_kh : g_vh;
        __nv_bfloat16* ol = (o == 0) ? g_ql : (o == 1) ? g_kl : g_vl;
        #pragma unroll
        for (int mt = 0; mt < 2; mt++)
            #pragma unroll
            for (int nt = 0; nt < 4; nt++) {
                const int row = m0 + warp_m * 32 + mt * 16 + frow;
                const int col = warp_n * 32 + nt * 8 + fcol;
                uint32_t h01, l01, h23, l23;
                split_pack_fast(acc[o][mt][nt][0], acc[o][mt][nt][1], h01, l01);
                split_pack_fast(acc[o][mt][nt][2], acc[o][mt][nt][3], h23, l23);
                *(uint32_t*)(oh + (size_t)row * DH + col) = h01;
                *(uint32_t*)(ol + (size_t)row * DH + col) = l01;
                *(uint32_t*)(oh + (size_t)(row + 8) * DH + col) = h23;
                *(uint32_t*)(ol + (size_t)(row + 8) * DH + col) = l23;
            }
    }
}

// ===========================================================================
// HMMA split-KV flash attention. Br=128, Bc=64, 256 thr.
// Single barrier/tile; exp2 softmax; fused pack+PV; causal warp-tile skipping.
// ===========================================================================
#define AST 72
#define AT_QH 0
#define AT_QL 9216
#define AT_TB 18432
#define AT_TBSZ 18432
#define AT_SMEM ((AT_TB + 2 * AT_TBSZ) * 2)   // 110592 bytes

__device__ __forceinline__ void at_load(uint32_t sbase, int b, int j0, int buf)
{
    const int tid = threadIdx.x;
    const uint32_t bb = sbase + (AT_TB + buf * AT_TBSZ) * 2;
    #pragma unroll
    for (int i = 0; i < 2; i++) {
        const int idx = tid + 256 * i;
        const int r = idx >> 3, g = idx & 7;
        const size_t go = (size_t)(b * TT + j0 + r) * DH + g * 8;
        const uint32_t so = (r * AST + g * 8) * 2;
        cp16(bb + so,         g_kh + go);
        cp16(bb + 9216 + so,  g_kl + go);
        cp16(bb + 18432 + so, g_vh + go);
        cp16(bb + 27648 + so, g_vl + go);
    }
}

__global__ void __launch_bounds__(256) attn_mma_kernel(
    const float* __restrict__ rel_emb)
{
    const int rt    = 31 - blockIdx.x;   // big rt first
    const int chunk = blockIdx.y;
    const int b     = blockIdx.z;
    const int ct0   = chunk * 8;
    const int ctmax = 2 * rt + 1;
    if (ct0 > ctmax) return;
    const int ct1 = min(ctmax, ct0 + 7);

    extern __shared__ char smemb[];
    const uint32_t sbase = smem_u32(smemb);
    __shared__ float sRel[17];

    const int tid = threadIdx.x;
    const int w = tid >> 5, lane = tid & 31;
    const int i0 = rt * 128;

    if (tid < 17) sRel[tid] = rel_emb[tid] * LOG2E;
    const float SCL = 0.125f * LOG2E;

    #pragma unroll
    for (int it = 0; it < 4; it++) {
        const int idx = tid + 256 * it;
        const int r = idx >> 3, g = idx & 7;
        const size_t go = (size_t)(b * TT + i0 + r) * DH + g * 8;
        const uint32_t so = (r * AST + g * 8) * 2;
        cp16(sbase + AT_QH * 2 + so, g_qh + go);
        cp16(sbase + AT_QL * 2 + so, g_ql + go);
    }
    at_load(sbase, b, ct0 * 64, 0);
    CP_COMMIT();

    const int arow = lane & 15, ahalf = lane >> 4;
    const int bq = lane >> 3, bw = lane & 7;
    const int brow = (bq >> 1) * 8 + bw;
    const int bk = (bq & 1) * 8;
    const int frow = lane >> 2, fcol = (lane & 3) * 2;
    const int vrow = (bq & 1) * 8 + bw;
    const int vcol = (bq >> 1) * 8;

    float oacc[8][4];
    #pragma unroll
    for (int nt = 0; nt < 8; nt++)
        #pragma unroll
        for (int e = 0; e < 4; e++) oacc[nt][e] = 0.f;
    float l0 = 0.f, l1 = 0.f;

    for (int ct = ct0; ct <= ct1; ct++) {
        const int buf = (ct - ct0) & 1;
        CP_WAIT0();
        __syncthreads();
        if (ct < ct1) {
            at_load(sbase, b, (ct + 1) * 64, buf ^ 1);
            CP_COMMIT();
        }

        const uint32_t tb = sbase + (AT_TB + buf * AT_TBSZ) * 2;
        const int j0 = ct * 64;

        if (ct < 2 * rt) {
            // ================= full-compute path (no causal mask) ==========
            float sacc[8][4];
            #pragma unroll
            for (int nt = 0; nt < 8; nt++)
                #pragma unroll
                for (int e = 0; e < 4; e++) sacc[nt][e] = 0.f;
            #pragma unroll
            for (int ks = 0; ks < 4; ks++) {
                const int kc = ks * 16;
                uint32_t ah[4], al[4];
                const uint32_t aaddr = sbase
                    + ((w * 16 + arow) * AST + kc + ahalf * 8) * 2;
                LDMX4(ah, aaddr + AT_QH * 2);
                LDMX4(al, aaddr + AT_QL * 2);
                #pragma unroll
                for (int nt16 = 0; nt16 < 4; nt16++) {
                    uint32_t bh[4], bl[4];
                    const uint32_t baddr = tb + ((nt16 * 16 + brow) * AST + kc + bk) * 2;
                    LDMX4(bh, baddr);
                    LDMX4(bl, baddr + 9216);
                    mma16816(sacc[2 * nt16],     ah, bh[0], bh[1]);
                    mma16816(sacc[2 * nt16 + 1], ah, bh[2], bh[3]);
                    mma16816(sacc[2 * nt16],     ah, bl[0], bl[1]);
                    mma16816(sacc[2 * nt16 + 1], ah, bl[2], bl[3]);
                    mma16816(sacc[2 * nt16],     al, bh[0], bh[1]);
                    mma16816(sacc[2 * nt16 + 1], al, bh[2], bh[3]);
                }
            }

            float e[8][4];
            if (ct <= 2 * rt - 2) {
                const float b0v = sRel[0];
                #pragma unroll
                for (int nt = 0; nt < 8; nt++)
                    #pragma unroll
                    for (int u = 0; u < 4; u++)
                        e[nt][u] = ex2f(fmaf(sacc[nt][u], SCL, b0v));
            } else {
                // ct == 2rt-1: d in [-191, -1]; bias lookup, no mask
                const int ia = i0 + w * 16 + frow;
                #pragma unroll
                for (int nt = 0; nt < 8; nt++) {
                    const int jb2 = j0 + nt * 8 + fcol;
                    #pragma unroll
                    for (int u = 0; u < 4; u++) {
                        const int d = (jb2 + (u & 1)) - (ia + (u >> 1) * 8);
                        e[nt][u] = ex2f(fmaf(sacc[nt][u], SCL,
                                             sRel[(d < -8 ? -8 : d) + 8]));
                    }
                }
            }
            #pragma unroll
            for (int nt = 0; nt < 8; nt++) {
                l0 += e[nt][0] + e[nt][1];
                l1 += e[nt][2] + e[nt][3];
            }

            // fused pack + PV per js chunk
            #pragma unroll
            for (int t = 0; t < 4; t++) {
                uint32_t ph[4], pl[4];
                split_pack_fast(e[2 * t][0],     e[2 * t][1],     ph[0], pl[0]);
                split_pack_fast(e[2 * t][2],     e[2 * t][3],     ph[1], pl[1]);
                split_pack_fast(e[2 * t + 1][0], e[2 * t + 1][1], ph[2], pl[2]);
                split_pack_fast(e[2 * t + 1][2], e[2 * t + 1][3], ph[3], pl[3]);
                const int jc = t * 16;
                #pragma unroll
                for (int h16 = 0; h16 < 4; h16++) {
                    uint32_t vh4[4], vl4[4];
                    const uint32_t vaddr = tb
                        + ((jc + vrow) * AST + h16 * 16 + vcol) * 2;
                    LDMX4T(vh4, vaddr + 18432);
                    LDMX4T(vl4, vaddr + 27648);
                    mma16816(oacc[2 * h16],     ph, vh4[0], vh4[1]);
                    mma16816(oacc[2 * h16 + 1], ph, vh4[2], vh4[3]);
                    mma16816(oacc[2 * h16],     ph, vl4[0], vl4[1]);
                    mma16816(oacc[2 * h16 + 1], ph, vl4[2], vl4[3]);
                    mma16816(oacc[2 * h16],     pl, vh4[0], vh4[1]);
                    mma16816(oacc[2 * h16 + 1], pl, vh4[2], vh4[3]);
                }
            }
        } else {
            // ============ diagonal tiles: warp-level chunk skipping ========
            const int ntm0 = w - ((j0 - i0) >> 4);
            const int ntmax = ntm0 < 3 ? ntm0 : 3;
            if (ntmax >= 0) {
                float sacc[8][4];
                #pragma unroll
                for (int nt = 0; nt < 8; nt++)
                    #pragma unroll
                    for (int e = 0; e < 4; e++) sacc[nt][e] = 0.f;
                #pragma unroll
                for (int ks = 0; ks < 4; ks++) {
                    const int kc = ks * 16;
                    uint32_t ah[4], al[4];
                    const uint32_t aaddr = sbase
                        + ((w * 16 + arow) * AST + kc + ahalf * 8) * 2;
                    LDMX4(ah, aaddr + AT_QH * 2);
                    LDMX4(al, aaddr + AT_QL * 2);
                    for (int nt16 = 0; nt16 <= ntmax; nt16++) {
                        uint32_t bh[4], bl[4];
                        const uint32_t baddr = tb
                            + ((nt16 * 16 + brow) * AST + kc + bk) * 2;
                        LDMX4(bh, baddr);
                        LDMX4(bl, baddr + 9216);
                        mma16816(sacc[2 * nt16],     ah, bh[0], bh[1]);
                        mma16816(sacc[2 * nt16 + 1], ah, bh[2], bh[3]);
                        mma16816(sacc[2 * nt16],     ah, bl[0], bl[1]);
                        mma16816(sacc[2 * nt16 + 1], ah, bl[2], bl[3]);
                        mma16816(sacc[2 * nt16],     al, bh[0], bh[1]);
                        mma16816(sacc[2 * nt16 + 1], al, bh[2], bh[3]);
                    }
                }

                const int ia = i0 + w * 16 + frow;
                for (int t = 0; t <= ntmax; t++) {
                    float e[2][4];
                    #pragma unroll
                    for (int p = 0; p < 2; p++) {
                        const int nt = 2 * t + p;
                        const int jb2 = j0 + nt * 8 + fcol;
                        #pragma unroll
                        for (int u = 0; u < 4; u++) {
                            const int d = (jb2 + (u & 1)) - (ia + (u >> 1) * 8);
                            e[p][u] = (d <= 0)
                                ? ex2f(fmaf(sacc[nt][u], SCL,
                                            sRel[(d < -8 ? -8 : d) + 8]))
                                : 0.f;
                        }
                    }
                    l0 += e[0][0] + e[0][1] + e[1][0] + e[1][1];
                    l1 += e[0][2] + e[0][3] + e[1][2] + e[1][3];

                    uint32_t ph[4], pl[4];
                    split_pack_fast(e[0][0], e[0][1], ph[0], pl[0]);
                    split_pack_fast(e[0][2], e[0][3], ph[1], pl[1]);
                    split_pack_fast(e[1][0], e[1][1], ph[2], pl[2]);
                    split_pack_fast(e[1][2], e[1][3], ph[3], pl[3]);
                    const int jc = t * 16;
                    #pragma unroll
                    for (int h16 = 0; h16 < 4; h16++) {
                        uint32_t vh4[4], vl4[4];
                        const uint32_t vaddr = tb
                            + ((jc + vrow) * AST + h16 * 16 + vcol) * 2;
                        LDMX4T(vh4, vaddr + 18432);
                        LDMX4T(vl4, vaddr + 27648);
                        mma16816(oacc[2 * h16],     ph, vh4[0], vh4[1]);
                        mma16816(oacc[2 * h16 + 1], ph, vh4[2], vh4[3]);
                        mma16816(oacc[2 * h16],     ph, vl4[0], vl4[1]);
                        mma16816(oacc[2 * h16 + 1], ph, vl4[2], vl4[3]);
                        mma16816(oacc[2 * h16],     pl, vh4[0], vh4[1]);
                        mma16816(oacc[2 * h16 + 1], pl, vh4[2], vh4[3]);
                    }
                }
            }
        }
    }

    // reduce l within quads (lanes sharing rows)
    l0 += __shfl_xor_sync(0xffffffffu, l0, 1);
    l0 += __shfl_xor_sync(0xffffffffu, l0, 2);
    l1 += __shfl_xor_sync(0xffffffffu, l1, 1);
    l1 += __shfl_xor_sync(0xffffffffu, l1, 2);

    // write partials
    const size_t unit = ((size_t)(b * 32 + rt) * 8 + chunk);
    float* po = g_po + unit * 128 * 64;
    const int row = w * 16 + frow;
    #pragma unroll
    for (int nt = 0; nt < 8; nt++) {
        const int col = nt * 8 + fcol;
        *(float2*)(po + (size_t)row * 64 + col) =
            make_float2(oacc[nt][0], oacc[nt][1]);
        *(float2*)(po + (size_t)(row + 8) * 64 + col) =
            make_float2(oacc[nt][2], oacc[nt][3]);
    }
    if ((lane & 3) == 0) {
        g_pl[unit * 128 + row] = l0;
        g_pl[unit * 128 + row + 8] = l1;
    }
}

// ---------------------------------------------------------------------------
// Combine partials: out = (sum_p O_p) / (sum_p l_p).
// Block = (rt, b, col-quarter): 512 blocks, 8 floats per thread.
// ---------------------------------------------------------------------------
__global__ void __launch_bounds__(256) combine_kernel(float* __restrict__ out)
{
    const int rt  = blockIdx.x;
    const int b   = blockIdx.y;
    const int nch = (2 * rt + 9) >> 3;
    const size_t base = (size_t)(b * 32 + rt) * 8;

    __shared__ float sInvL[128];

    const int tid = threadIdx.x;
    if (tid < 128) {
        float L = 0.f;
        for (int p = 0; p < nch; p++)
            L += g_pl[(base + p) * 128 + tid];
        sInvL[tid] = 1.0f / L;
    }
    __syncthreads();

    const int r  = tid >> 1;
    const int h0 = blockIdx.z * 16 + (tid & 1) * 8;
    float acc[8] = {};
    for (int p = 0; p < nch; p++) {
        const float* po = g_po + ((base + p) * 128 + r) * 64 + h0;
        float4 v0 = *(const float4*)(po);
        float4 v1 = *(const float4*)(po + 4);
        acc[0] += v0.x; acc[1] += v0.y; acc[2] += v0.z; acc[3] += v0.w;
        acc[4] += v1.x; acc[5] += v1.y; acc[6] += v1.z; acc[7] += v1.w;
    }
    const float inv = sInvL[r];
    float* op = out + (size_t)(b * TT + rt * 128 + r) * DH + h0;
    *(float4*)(op)     = make_float4(acc[0] * inv, acc[1] * inv,
                                     acc[2] * inv, acc[3] * inv);
    *(float4*)(op + 4) = make_float4(acc[4] * inv, acc[5] * inv,
                                     acc[6] * inv, acc[7] * inv);
}

extern "C" void kernel_launch(void* const* d_in, const int* in_sizes, int n_in,
                              void* d_out, int out_size)
{
    const float* x   = (const float*)d_in[0];
    const float* Wq  = (const float*)d_in[1];
    const float* Wk  = (const float*)d_in[2];
    const float* Wv  = (const float*)d_in[3];
    const float* rel = (const float*)d_in[4];
    float* out = (float*)d_out;

    dim3 wgrid(64, 3);
    convert_w_kernel<<<wgrid, 256>>>(Wq, Wk, Wv);

    cudaFuncSetAttribute(proj_mma_kernel,
                         cudaFuncAttributeMaxDynamicSharedMemorySize, PJ_SMEM);
    proj_mma_kernel<<<128, 256, PJ_SMEM>>>(x);

    cudaFuncSetAttribute(attn_mma_kernel,
                         cudaFuncAttributeMaxDynamicSharedMemorySize, AT_SMEM);
    dim3 agrid(32, 8, BB);
    attn_mma_kernel<<<agrid, 256, AT_SMEM>>>(rel);

    dim3 cgrid(32, BB, 4);
    combine_kernel<<<cgrid, 256>>>(out);
}